// round 7
// baseline (speedup 1.0000x reference)
#include <cuda_runtime.h>

#define C 64
#define MAXN 50000
#define MAXE 800000
#define SCAN_T 1024
#define SCAN_CH 49                 // 1024*49 = 50176 >= MAXN
#define SCAN_PAD (SCAN_T * SCAN_CH)

// Scratch (allocation-free, graph-safe).
__device__ int   g_cnt[MAXN];                    // per-target degree
__device__ int   g_off[MAXN];                    // exclusive CSR offsets
__device__ float g_dis[MAXN];                    // deg_inv_sqrt
__device__ int   g_rank[MAXE];                   // edge's rank within its target
__device__ int   g_srcid[MAXE];                  // CSR: source node per slot
__device__ __align__(16) float g_h[MAXN * C];    // h = x @ W^T

// Zero degree counts.
__global__ void k_zero(int N) {
    int i = blockIdx.x * blockDim.x + threadIdx.x;
    if (i < N) g_cnt[i] = 0;
}

// Degree histogram; atomicAdd's return value is this edge's rank within its target.
__global__ void k_deg(const int* __restrict__ tgt, int E) {
    int i = blockIdx.x * blockDim.x + threadIdx.x;
    if (i < E) g_rank[i] = atomicAdd(&g_cnt[tgt[i]], 1);
}

// Fused single-block exclusive scan over g_cnt (+ deg_inv_sqrt).
// All counts staged in dynamic smem; thread t owns contiguous chunk [t*49, t*49+49).
__global__ void __launch_bounds__(SCAN_T) k_scan(int N) {
    extern __shared__ int sh[];                  // SCAN_PAD ints
    __shared__ int wsum[32];
    __shared__ int wpre[32];
    int t = threadIdx.x;
    for (int i = t; i < SCAN_PAD; i += SCAN_T) sh[i] = (i < N) ? g_cnt[i] : 0;
    __syncthreads();

    int base = t * SCAN_CH;
    int s = 0;
    #pragma unroll
    for (int i = 0; i < SCAN_CH; i++) s += sh[base + i];   // stride-49: conflict-free

    // Block-wide exclusive scan of per-thread sums (warp shfl + 32 partials).
    int lane = t & 31, wid = t >> 5;
    int v = s;
    #pragma unroll
    for (int d = 1; d < 32; d <<= 1) {
        int u = __shfl_up_sync(0xffffffffu, v, d);
        if (lane >= d) v += u;
    }
    if (lane == 31) wsum[wid] = v;
    __syncthreads();
    if (wid == 0) {
        int wv = (lane < 32) ? wsum[lane] : 0;
        #pragma unroll
        for (int d = 1; d < 32; d <<= 1) {
            int u = __shfl_up_sync(0xffffffffu, wv, d);
            if (lane >= d) wv += u;
        }
        wpre[lane] = wv;
    }
    __syncthreads();
    int prefix = (wid ? wpre[wid - 1] : 0) + (v - s);      // exclusive over threads

    int running = prefix;
    #pragma unroll
    for (int i = 0; i < SCAN_CH; i++) {
        int idx = base + i;
        if (idx < N) {
            int c = sh[idx];
            g_off[idx] = running;
            g_dis[idx] = rsqrtf(fmaxf((float)c, 1.0f));
            running += c;
        }
    }
}

// CSR fill, no atomics: position = off[tgt] + rank.
__global__ void k_fill(const int* __restrict__ src, const int* __restrict__ tgt, int E) {
    int i = blockIdx.x * blockDim.x + threadIdx.x;
    if (i >= E) return;
    g_srcid[g_off[tgt[i]] + g_rank[i]] = src[i];
}

// h = x @ W^T (no bias/relu; linearity lets us aggregate h instead of x).
__global__ void __launch_bounds__(64) k_h(const float* __restrict__ x,
                                          const float* __restrict__ W, int N) {
    __shared__ float Ws[C * C];        // Ws[k*64 + j] = W[j*64 + k]
    __shared__ float As[64][C + 1];
    int tid = threadIdx.x;

    for (int idx = tid; idx < C * C; idx += 64) {
        int j = idx >> 6, k = idx & 63;
        Ws[k * C + j] = W[idx];
    }
    int base = blockIdx.x * 64;
    for (int idx = tid; idx < 64 * 16; idx += 64) {
        int i = idx >> 4, j4 = idx & 15;
        int r = base + i;
        float4 v = (r < N) ? ((const float4*)(x + (size_t)r * C))[j4]
                           : make_float4(0.f, 0.f, 0.f, 0.f);
        As[i][j4 * 4 + 0] = v.x;
        As[i][j4 * 4 + 1] = v.y;
        As[i][j4 * 4 + 2] = v.z;
        As[i][j4 * 4 + 3] = v.w;
    }
    __syncthreads();

    float acc[C];
    #pragma unroll
    for (int j = 0; j < C; j++) acc[j] = 0.0f;

    for (int k = 0; k < C; k++) {
        float ak = As[tid][k];
        const float4* wr = (const float4*)(Ws + k * C);
        #pragma unroll
        for (int j4 = 0; j4 < 16; j4++) {
            float4 w = wr[j4];
            acc[4 * j4 + 0] += ak * w.x;
            acc[4 * j4 + 1] += ak * w.y;
            acc[4 * j4 + 2] += ak * w.z;
            acc[4 * j4 + 3] += ak * w.w;
        }
    }

    int node = base + tid;
    if (node < N) {
        float4* o = (float4*)(g_h + (size_t)node * C);
        #pragma unroll
        for (int j4 = 0; j4 < 16; j4++)
            o[j4] = make_float4(acc[4 * j4], acc[4 * j4 + 1], acc[4 * j4 + 2], acc[4 * j4 + 3]);
    }
}

// Aggregate h over CSR + bias + relu, writing d_out directly.
// One warp per node; srcid+dis prefetched lane-parallel, broadcast via shfl,
// so the inner loop's only memory op is the independent float2 gather of h.
__global__ void k_aggrelu(const float* __restrict__ bias, float* __restrict__ out, int N) {
    int w = (blockIdx.x * blockDim.x + threadIdx.x) >> 5;
    int lane = threadIdx.x & 31;
    if (w >= N) return;
    int off = g_off[w];
    int cnt = g_cnt[w];
    const float* hp = g_h + lane * 2;
    float a0 = 0.0f, a1 = 0.0f;

    for (int base = 0; base < cnt; base += 32) {
        int m = cnt - base;
        if (m > 32) m = 32;
        int   s  = (lane < m) ? g_srcid[off + base + lane] : 0;
        float ws = (lane < m) ? g_dis[s] : 0.0f;
        if (m == 32) {
            #pragma unroll 8
            for (int e = 0; e < 32; e++) {
                int   se = __shfl_sync(0xffffffffu, s, e);
                float we = __shfl_sync(0xffffffffu, ws, e);
                float2 v = *(const float2*)(hp + (size_t)se * C);
                a0 += we * v.x;
                a1 += we * v.y;
            }
        } else {
            for (int e = 0; e < m; e++) {
                int   se = __shfl_sync(0xffffffffu, s, e);
                float we = __shfl_sync(0xffffffffu, ws, e);
                float2 v = *(const float2*)(hp + (size_t)se * C);
                a0 += we * v.x;
                a1 += we * v.y;
            }
        }
    }

    float dn = g_dis[w];
    float2 bb = *(const float2*)(bias + lane * 2);
    float2 r;
    r.x = fmaxf(a0 * dn + bb.x, 0.0f);
    r.y = fmaxf(a1 * dn + bb.y, 0.0f);
    *(float2*)(out + (size_t)w * C + lane * 2) = r;
}

extern "C" void kernel_launch(void* const* d_in, const int* in_sizes, int n_in,
                              void* d_out, int out_size) {
    const float* x   = (const float*)d_in[0];
    const int*   ei  = (const int*)d_in[1];     // int32, [2, E] row-major
    const float* W   = (const float*)d_in[2];
    const float* b   = (const float*)d_in[3];
    float*       out = (float*)d_out;

    int N = in_sizes[0] / C;     // 50000
    int E = in_sizes[1] / 2;     // 800000
    const int* src = ei;
    const int* tgt = ei + E;

    int scan_smem = SCAN_PAD * (int)sizeof(int);      // ~200 KB
    cudaFuncSetAttribute(k_scan, cudaFuncAttributeMaxDynamicSharedMemorySize, scan_smem);

    k_zero<<<(N + 255) / 256, 256>>>(N);
    k_deg<<<(E + 255) / 256, 256>>>(tgt, E);
    k_scan<<<1, SCAN_T, scan_smem>>>(N);
    k_fill<<<(E + 255) / 256, 256>>>(src, tgt, E);
    k_h<<<(N + 63) / 64, 64>>>(x, W, N);

    long long T = (long long)N * 32;
    k_aggrelu<<<(int)((T + 255) / 256), 256>>>(b, out, N);
}

// round 8
// speedup vs baseline: 1.0207x; 1.0207x over previous
#include <cuda_runtime.h>

#define C 64
#define MAXN 50000
#define MAXE 800000
#define SCAN_T 1024
#define SCAN_CH 49                 // 1024*49 = 50176 >= MAXN
#define SCAN_PAD (SCAN_T * SCAN_CH)

// Scratch (allocation-free, graph-safe).
__device__ int   g_cnt[MAXN];                    // per-target degree
__device__ int   g_off[MAXN];                    // exclusive CSR offsets
__device__ float g_dis[MAXN];                    // deg_inv_sqrt
__device__ int   g_rank[MAXE];                   // edge's rank within its target
__device__ int   g_srcid[MAXE];                  // CSR: source node per slot
__device__ __align__(16) float g_h[MAXN * C];    // h = x @ W^T

// Zero degree counts.
__global__ void k_zero(int N) {
    int i = blockIdx.x * blockDim.x + threadIdx.x;
    if (i < N) g_cnt[i] = 0;
}

// Degree histogram; atomicAdd's return value is this edge's rank within its target.
__global__ void k_deg(const int* __restrict__ tgt, int E) {
    int i = blockIdx.x * blockDim.x + threadIdx.x;
    if (i < E) g_rank[i] = atomicAdd(&g_cnt[tgt[i]], 1);
}

// Fused single-block exclusive scan over g_cnt (+ deg_inv_sqrt).
__global__ void __launch_bounds__(SCAN_T) k_scan(int N) {
    extern __shared__ int sh[];                  // SCAN_PAD ints
    __shared__ int wsum[32];
    __shared__ int wpre[32];
    int t = threadIdx.x;
    for (int i = t; i < SCAN_PAD; i += SCAN_T) sh[i] = (i < N) ? g_cnt[i] : 0;
    __syncthreads();

    int base = t * SCAN_CH;
    int s = 0;
    #pragma unroll
    for (int i = 0; i < SCAN_CH; i++) s += sh[base + i];   // stride-49: conflict-free

    int lane = t & 31, wid = t >> 5;
    int v = s;
    #pragma unroll
    for (int d = 1; d < 32; d <<= 1) {
        int u = __shfl_up_sync(0xffffffffu, v, d);
        if (lane >= d) v += u;
    }
    if (lane == 31) wsum[wid] = v;
    __syncthreads();
    if (wid == 0) {
        int wv = (lane < 32) ? wsum[lane] : 0;
        #pragma unroll
        for (int d = 1; d < 32; d <<= 1) {
            int u = __shfl_up_sync(0xffffffffu, wv, d);
            if (lane >= d) wv += u;
        }
        wpre[lane] = wv;
    }
    __syncthreads();
    int prefix = (wid ? wpre[wid - 1] : 0) + (v - s);      // exclusive over threads

    int running = prefix;
    #pragma unroll
    for (int i = 0; i < SCAN_CH; i++) {
        int idx = base + i;
        if (idx < N) {
            int c = sh[idx];
            g_off[idx] = running;
            g_dis[idx] = rsqrtf(fmaxf((float)c, 1.0f));
            running += c;
        }
    }
}

// CSR fill, no atomics: position = off[tgt] + rank.
__global__ void k_fill(const int* __restrict__ src, const int* __restrict__ tgt, int E) {
    int i = blockIdx.x * blockDim.x + threadIdx.x;
    if (i >= E) return;
    g_srcid[g_off[tgt[i]] + g_rank[i]] = src[i];
}

// h = x @ W^T (no bias/relu; linearity lets us aggregate h instead of x).
__global__ void __launch_bounds__(64) k_h(const float* __restrict__ x,
                                          const float* __restrict__ W, int N) {
    __shared__ float Ws[C * C];        // Ws[k*64 + j] = W[j*64 + k]
    __shared__ float As[64][C + 1];
    int tid = threadIdx.x;

    for (int idx = tid; idx < C * C; idx += 64) {
        int j = idx >> 6, k = idx & 63;
        Ws[k * C + j] = W[idx];
    }
    int base = blockIdx.x * 64;
    for (int idx = tid; idx < 64 * 16; idx += 64) {
        int i = idx >> 4, j4 = idx & 15;
        int r = base + i;
        float4 v = (r < N) ? ((const float4*)(x + (size_t)r * C))[j4]
                           : make_float4(0.f, 0.f, 0.f, 0.f);
        As[i][j4 * 4 + 0] = v.x;
        As[i][j4 * 4 + 1] = v.y;
        As[i][j4 * 4 + 2] = v.z;
        As[i][j4 * 4 + 3] = v.w;
    }
    __syncthreads();

    float acc[C];
    #pragma unroll
    for (int j = 0; j < C; j++) acc[j] = 0.0f;

    for (int k = 0; k < C; k++) {
        float ak = As[tid][k];
        const float4* wr = (const float4*)(Ws + k * C);
        #pragma unroll
        for (int j4 = 0; j4 < 16; j4++) {
            float4 w = wr[j4];
            acc[4 * j4 + 0] += ak * w.x;
            acc[4 * j4 + 1] += ak * w.y;
            acc[4 * j4 + 2] += ak * w.z;
            acc[4 * j4 + 3] += ak * w.w;
        }
    }

    int node = base + tid;
    if (node < N) {
        float4* o = (float4*)(g_h + (size_t)node * C);
        #pragma unroll
        for (int j4 = 0; j4 < 16; j4++)
            o[j4] = make_float4(acc[4 * j4], acc[4 * j4 + 1], acc[4 * j4 + 2], acc[4 * j4 + 3]);
    }
}

// Aggregate h over CSR + bias + relu, writing d_out directly.
// One warp per node; warp-uniform scalar loads of srcid/dis (broadcast, L1-hit),
// independent float2 gathers of h, unroll-4 for MLP.
__global__ void k_aggrelu(const float* __restrict__ bias, float* __restrict__ out, int N) {
    int w = (blockIdx.x * blockDim.x + threadIdx.x) >> 5;
    int lane = threadIdx.x & 31;
    if (w >= N) return;
    int off = g_off[w];
    int cnt = g_cnt[w];
    const float* hp = g_h + lane * 2;
    float a0 = 0.0f, a1 = 0.0f;
    int i = 0;
    for (; i + 4 <= cnt; i += 4) {
        int s0 = g_srcid[off + i];
        int s1 = g_srcid[off + i + 1];
        int s2 = g_srcid[off + i + 2];
        int s3 = g_srcid[off + i + 3];
        float w0 = g_dis[s0];
        float w1 = g_dis[s1];
        float w2 = g_dis[s2];
        float w3 = g_dis[s3];
        float2 v0 = *(const float2*)(hp + (size_t)s0 * C);
        float2 v1 = *(const float2*)(hp + (size_t)s1 * C);
        float2 v2 = *(const float2*)(hp + (size_t)s2 * C);
        float2 v3 = *(const float2*)(hp + (size_t)s3 * C);
        a0 += w0 * v0.x + w1 * v1.x + w2 * v2.x + w3 * v3.x;
        a1 += w0 * v0.y + w1 * v1.y + w2 * v2.y + w3 * v3.y;
    }
    for (; i < cnt; i++) {
        int s = g_srcid[off + i];
        float ws = g_dis[s];
        float2 v = *(const float2*)(hp + (size_t)s * C);
        a0 += ws * v.x;
        a1 += ws * v.y;
    }

    float dn = g_dis[w];
    float2 bb = *(const float2*)(bias + lane * 2);
    float2 r;
    r.x = fmaxf(a0 * dn + bb.x, 0.0f);
    r.y = fmaxf(a1 * dn + bb.y, 0.0f);
    *(float2*)(out + (size_t)w * C + lane * 2) = r;
}

extern "C" void kernel_launch(void* const* d_in, const int* in_sizes, int n_in,
                              void* d_out, int out_size) {
    const float* x   = (const float*)d_in[0];
    const int*   ei  = (const int*)d_in[1];     // int32, [2, E] row-major
    const float* W   = (const float*)d_in[2];
    const float* b   = (const float*)d_in[3];
    float*       out = (float*)d_out;

    int N = in_sizes[0] / C;     // 50000
    int E = in_sizes[1] / 2;     // 800000
    const int* src = ei;
    const int* tgt = ei + E;

    int scan_smem = SCAN_PAD * (int)sizeof(int);      // ~200 KB
    cudaFuncSetAttribute(k_scan, cudaFuncAttributeMaxDynamicSharedMemorySize, scan_smem);

    k_zero<<<(N + 255) / 256, 256>>>(N);
    k_deg<<<(E + 255) / 256, 256>>>(tgt, E);
    k_scan<<<1, SCAN_T, scan_smem>>>(N);
    k_fill<<<(E + 255) / 256, 256>>>(src, tgt, E);
    k_h<<<(N + 63) / 64, 64>>>(x, W, N);

    long long T = (long long)N * 32;
    k_aggrelu<<<(int)((T + 255) / 256), 256>>>(b, out, N);
}

// round 9
// speedup vs baseline: 1.4597x; 1.4300x over previous
#include <cuda_runtime.h>

#define C 64
#define MAXN 50000
#define MAXE 800000
#define SCAN_T 1024
#define SCAN_CH 49                 // 1024*49 = 50176 >= MAXN
#define SCAN_PAD (SCAN_T * SCAN_CH)

// Scratch (allocation-free, graph-safe).
__device__ int   g_cnt[MAXN];                    // per-target degree
__device__ int   g_off[MAXN];                    // exclusive CSR offsets
__device__ float g_dis[MAXN];                    // deg_inv_sqrt
__device__ int   g_rank[MAXE];                   // edge's rank within its target
__device__ int   g_srcid[MAXE];                  // CSR: source node per slot
__device__ __align__(16) float g_h[MAXN * C];    // h = x @ W^T

// Zero degree counts.
__global__ void k_zero(int N) {
    int i = blockIdx.x * blockDim.x + threadIdx.x;
    if (i < N) g_cnt[i] = 0;
}

// Degree histogram; atomicAdd's return value is this edge's rank within its target.
__global__ void k_deg(const int* __restrict__ tgt, int E) {
    int i = blockIdx.x * blockDim.x + threadIdx.x;
    if (i < E) g_rank[i] = atomicAdd(&g_cnt[tgt[i]], 1);
}

// Fused single-block exclusive scan over g_cnt (+ deg_inv_sqrt).
// Chunked layout for smem compute; COALESCED gmem write-out (the R7/R8 version's
// chunk-order writes were 32-way uncoalesced on a single SM: ~70us. Fixed here.)
__global__ void __launch_bounds__(SCAN_T) k_scan(int N) {
    extern __shared__ int sh[];                  // SCAN_PAD ints
    __shared__ int wsum[32];
    __shared__ int wpre[32];
    int t = threadIdx.x;
    for (int i = t; i < SCAN_PAD; i += SCAN_T) sh[i] = (i < N) ? g_cnt[i] : 0;
    __syncthreads();

    int base = t * SCAN_CH;
    int s = 0;
    #pragma unroll
    for (int i = 0; i < SCAN_CH; i++) s += sh[base + i];   // stride-49: conflict-free

    // Block-wide exclusive scan of per-thread chunk sums.
    int lane = t & 31, wid = t >> 5;
    int v = s;
    #pragma unroll
    for (int d = 1; d < 32; d <<= 1) {
        int u = __shfl_up_sync(0xffffffffu, v, d);
        if (lane >= d) v += u;
    }
    if (lane == 31) wsum[wid] = v;
    __syncthreads();
    if (wid == 0) {
        int wv = (lane < 32) ? wsum[lane] : 0;
        #pragma unroll
        for (int d = 1; d < 32; d <<= 1) {
            int u = __shfl_up_sync(0xffffffffu, wv, d);
            if (lane >= d) wv += u;
        }
        wpre[lane] = wv;
    }
    __syncthreads();
    int prefix = (wid ? wpre[wid - 1] : 0) + (v - s);      // exclusive over threads

    // Write exclusive prefixes back into smem in place (own chunk; no race).
    int running = prefix;
    #pragma unroll
    for (int i = 0; i < SCAN_CH; i++) {
        int c = sh[base + i];
        sh[base + i] = running;
        running += c;
    }
    __syncthreads();

    // Coalesced write-out; reread g_cnt coalesced (L2-hot) for deg_inv_sqrt.
    for (int i = t; i < N; i += SCAN_T) {
        g_off[i] = sh[i];
        g_dis[i] = rsqrtf(fmaxf((float)g_cnt[i], 1.0f));
    }
}

// CSR fill, no atomics: position = off[tgt] + rank.
__global__ void k_fill(const int* __restrict__ src, const int* __restrict__ tgt, int E) {
    int i = blockIdx.x * blockDim.x + threadIdx.x;
    if (i >= E) return;
    g_srcid[g_off[tgt[i]] + g_rank[i]] = src[i];
}

// h = x @ W^T (no bias/relu; linearity lets us aggregate h instead of x).
__global__ void __launch_bounds__(64) k_h(const float* __restrict__ x,
                                          const float* __restrict__ W, int N) {
    __shared__ float Ws[C * C];        // Ws[k*64 + j] = W[j*64 + k]
    __shared__ float As[64][C + 1];
    int tid = threadIdx.x;

    for (int idx = tid; idx < C * C; idx += 64) {
        int j = idx >> 6, k = idx & 63;
        Ws[k * C + j] = W[idx];
    }
    int base = blockIdx.x * 64;
    for (int idx = tid; idx < 64 * 16; idx += 64) {
        int i = idx >> 4, j4 = idx & 15;
        int r = base + i;
        float4 v = (r < N) ? ((const float4*)(x + (size_t)r * C))[j4]
                           : make_float4(0.f, 0.f, 0.f, 0.f);
        As[i][j4 * 4 + 0] = v.x;
        As[i][j4 * 4 + 1] = v.y;
        As[i][j4 * 4 + 2] = v.z;
        As[i][j4 * 4 + 3] = v.w;
    }
    __syncthreads();

    float acc[C];
    #pragma unroll
    for (int j = 0; j < C; j++) acc[j] = 0.0f;

    for (int k = 0; k < C; k++) {
        float ak = As[tid][k];
        const float4* wr = (const float4*)(Ws + k * C);
        #pragma unroll
        for (int j4 = 0; j4 < 16; j4++) {
            float4 w = wr[j4];
            acc[4 * j4 + 0] += ak * w.x;
            acc[4 * j4 + 1] += ak * w.y;
            acc[4 * j4 + 2] += ak * w.z;
            acc[4 * j4 + 3] += ak * w.w;
        }
    }

    int node = base + tid;
    if (node < N) {
        float4* o = (float4*)(g_h + (size_t)node * C);
        #pragma unroll
        for (int j4 = 0; j4 < 16; j4++)
            o[j4] = make_float4(acc[4 * j4], acc[4 * j4 + 1], acc[4 * j4 + 2], acc[4 * j4 + 3]);
    }
}

// Aggregate h over CSR + bias + relu, writing d_out directly.
// One warp per node; warp-uniform scalar loads of srcid/dis (broadcast, L1-hit),
// independent float2 gathers of h, unroll-4 for MLP.
__global__ void k_aggrelu(const float* __restrict__ bias, float* __restrict__ out, int N) {
    int w = (blockIdx.x * blockDim.x + threadIdx.x) >> 5;
    int lane = threadIdx.x & 31;
    if (w >= N) return;
    int off = g_off[w];
    int cnt = g_cnt[w];
    const float* hp = g_h + lane * 2;
    float a0 = 0.0f, a1 = 0.0f;
    int i = 0;
    for (; i + 4 <= cnt; i += 4) {
        int s0 = g_srcid[off + i];
        int s1 = g_srcid[off + i + 1];
        int s2 = g_srcid[off + i + 2];
        int s3 = g_srcid[off + i + 3];
        float w0 = g_dis[s0];
        float w1 = g_dis[s1];
        float w2 = g_dis[s2];
        float w3 = g_dis[s3];
        float2 v0 = *(const float2*)(hp + (size_t)s0 * C);
        float2 v1 = *(const float2*)(hp + (size_t)s1 * C);
        float2 v2 = *(const float2*)(hp + (size_t)s2 * C);
        float2 v3 = *(const float2*)(hp + (size_t)s3 * C);
        a0 += w0 * v0.x + w1 * v1.x + w2 * v2.x + w3 * v3.x;
        a1 += w0 * v0.y + w1 * v1.y + w2 * v2.y + w3 * v3.y;
    }
    for (; i < cnt; i++) {
        int s = g_srcid[off + i];
        float ws = g_dis[s];
        float2 v = *(const float2*)(hp + (size_t)s * C);
        a0 += ws * v.x;
        a1 += ws * v.y;
    }

    float dn = g_dis[w];
    float2 bb = *(const float2*)(bias + lane * 2);
    float2 r;
    r.x = fmaxf(a0 * dn + bb.x, 0.0f);
    r.y = fmaxf(a1 * dn + bb.y, 0.0f);
    *(float2*)(out + (size_t)w * C + lane * 2) = r;
}

extern "C" void kernel_launch(void* const* d_in, const int* in_sizes, int n_in,
                              void* d_out, int out_size) {
    const float* x   = (const float*)d_in[0];
    const int*   ei  = (const int*)d_in[1];     // int32, [2, E] row-major
    const float* W   = (const float*)d_in[2];
    const float* b   = (const float*)d_in[3];
    float*       out = (float*)d_out;

    int N = in_sizes[0] / C;     // 50000
    int E = in_sizes[1] / 2;     // 800000
    const int* src = ei;
    const int* tgt = ei + E;

    int scan_smem = SCAN_PAD * (int)sizeof(int);      // ~200 KB
    cudaFuncSetAttribute(k_scan, cudaFuncAttributeMaxDynamicSharedMemorySize, scan_smem);

    k_zero<<<(N + 255) / 256, 256>>>(N);
    k_deg<<<(E + 255) / 256, 256>>>(tgt, E);
    k_scan<<<1, SCAN_T, scan_smem>>>(N);
    k_fill<<<(E + 255) / 256, 256>>>(src, tgt, E);
    k_h<<<(N + 63) / 64, 64>>>(x, W, N);

    long long T = (long long)N * 32;
    k_aggrelu<<<(int)((T + 255) / 256), 256>>>(b, out, N);
}

// round 10
// speedup vs baseline: 1.6598x; 1.1371x over previous
#include <cuda_runtime.h>

#define C 64
#define MAXN 50000
#define MAXE 800000

// Scratch (allocation-free, graph-safe).
__device__ int   g_cnt[MAXN];                    // per-target degree
__device__ int   g_off[MAXN];                    // CSR segment starts (unordered)
__device__ float g_dis[MAXN];                    // deg_inv_sqrt
__device__ int   g_rank[MAXE];                   // edge's rank within its target
__device__ __align__(8) int2 g_es[MAXE];         // CSR slot: {src id, dis[src] bits}
__device__ int   g_total;                        // global segment cursor
__device__ __align__(16) float g_h[MAXN * C];    // h = x @ W^T

// h = x @ W^T, fused with zeroing of g_cnt/g_total (independent work, runs first).
__global__ void __launch_bounds__(64) k_h(const float* __restrict__ x,
                                          const float* __restrict__ W, int N) {
    __shared__ float Ws[C * C];        // Ws[k*64 + j] = W[j*64 + k]
    __shared__ float As[64][C + 1];
    int tid = threadIdx.x;
    int gt = blockIdx.x * 64 + tid;
    if (gt < N) g_cnt[gt] = 0;         // fused zeroing (grid covers >= N threads)
    if (gt == 0) g_total = 0;

    for (int idx = tid; idx < C * C; idx += 64) {
        int j = idx >> 6, k = idx & 63;
        Ws[k * C + j] = W[idx];
    }
    int base = blockIdx.x * 64;
    for (int idx = tid; idx < 64 * 16; idx += 64) {
        int i = idx >> 4, j4 = idx & 15;
        int r = base + i;
        float4 v = (r < N) ? ((const float4*)(x + (size_t)r * C))[j4]
                           : make_float4(0.f, 0.f, 0.f, 0.f);
        As[i][j4 * 4 + 0] = v.x;
        As[i][j4 * 4 + 1] = v.y;
        As[i][j4 * 4 + 2] = v.z;
        As[i][j4 * 4 + 3] = v.w;
    }
    __syncthreads();

    float acc[C];
    #pragma unroll
    for (int j = 0; j < C; j++) acc[j] = 0.0f;

    for (int k = 0; k < C; k++) {
        float ak = As[tid][k];
        const float4* wr = (const float4*)(Ws + k * C);
        #pragma unroll
        for (int j4 = 0; j4 < 16; j4++) {
            float4 w = wr[j4];
            acc[4 * j4 + 0] += ak * w.x;
            acc[4 * j4 + 1] += ak * w.y;
            acc[4 * j4 + 2] += ak * w.z;
            acc[4 * j4 + 3] += ak * w.w;
        }
    }

    int node = base + tid;
    if (node < N) {
        float4* o = (float4*)(g_h + (size_t)node * C);
        #pragma unroll
        for (int j4 = 0; j4 < 16; j4++)
            o[j4] = make_float4(acc[4 * j4], acc[4 * j4 + 1], acc[4 * j4 + 2], acc[4 * j4 + 3]);
    }
}

// Degree histogram; atomicAdd's return value is this edge's rank within its target.
__global__ void k_deg(const int* __restrict__ tgt, int E) {
    int i = blockIdx.x * blockDim.x + threadIdx.x;
    if (i < E) g_rank[i] = atomicAdd(&g_cnt[tgt[i]], 1);
}

// Scan-free offsets: warp-scan of counts + one warp-aggregated atomic on a
// global cursor. Segments are contiguous (order unimportant). Also deg_inv_sqrt.
__global__ void k_off(int N) {
    int i = blockIdx.x * blockDim.x + threadIdx.x;
    int lane = threadIdx.x & 31;
    int c = (i < N) ? g_cnt[i] : 0;
    int v = c;
    #pragma unroll
    for (int d = 1; d < 32; d <<= 1) {
        int u = __shfl_up_sync(0xffffffffu, v, d);
        if (lane >= d) v += u;
    }
    int wtot = __shfl_sync(0xffffffffu, v, 31);       // warp total
    int wbase = 0;
    if (lane == 31) wbase = atomicAdd(&g_total, wtot);
    wbase = __shfl_sync(0xffffffffu, wbase, 31);
    if (i < N) {
        g_off[i] = wbase + v - c;                     // exclusive within warp
        g_dis[i] = rsqrtf(fmaxf((float)c, 1.0f));
    }
}

// CSR fill, no atomics: slot = off[tgt] + rank. Packs {src, dis[src]} so the
// aggregation loop has zero scattered scalar loads.
__global__ void k_fill(const int* __restrict__ src, const int* __restrict__ tgt, int E) {
    int i = blockIdx.x * blockDim.x + threadIdx.x;
    if (i >= E) return;
    int s = src[i];
    int pos = g_off[tgt[i]] + g_rank[i];
    g_es[pos] = make_int2(s, __float_as_int(g_dis[s]));
}

// Aggregate h over CSR + bias + relu, writing d_out directly.
// One warp per node; uniform 8B loads of {src,weight}, independent float2
// gathers of h rows, unroll-4 for MLP.
__global__ void k_aggrelu(const float* __restrict__ bias, float* __restrict__ out, int N) {
    int w = (blockIdx.x * blockDim.x + threadIdx.x) >> 5;
    int lane = threadIdx.x & 31;
    if (w >= N) return;
    int off = g_off[w];
    int cnt = g_cnt[w];
    const float* hp = g_h + lane * 2;
    float a0 = 0.0f, a1 = 0.0f;
    int i = 0;
    for (; i + 4 <= cnt; i += 4) {
        int2 e0 = g_es[off + i];
        int2 e1 = g_es[off + i + 1];
        int2 e2 = g_es[off + i + 2];
        int2 e3 = g_es[off + i + 3];
        float2 v0 = *(const float2*)(hp + (size_t)e0.x * C);
        float2 v1 = *(const float2*)(hp + (size_t)e1.x * C);
        float2 v2 = *(const float2*)(hp + (size_t)e2.x * C);
        float2 v3 = *(const float2*)(hp + (size_t)e3.x * C);
        float w0 = __int_as_float(e0.y);
        float w1 = __int_as_float(e1.y);
        float w2 = __int_as_float(e2.y);
        float w3 = __int_as_float(e3.y);
        a0 += w0 * v0.x + w1 * v1.x + w2 * v2.x + w3 * v3.x;
        a1 += w0 * v0.y + w1 * v1.y + w2 * v2.y + w3 * v3.y;
    }
    for (; i < cnt; i++) {
        int2 e = g_es[off + i];
        float2 v = *(const float2*)(hp + (size_t)e.x * C);
        float ws = __int_as_float(e.y);
        a0 += ws * v.x;
        a1 += ws * v.y;
    }

    float dn = g_dis[w];
    float2 bb = *(const float2*)(bias + lane * 2);
    float2 r;
    r.x = fmaxf(a0 * dn + bb.x, 0.0f);
    r.y = fmaxf(a1 * dn + bb.y, 0.0f);
    *(float2*)(out + (size_t)w * C + lane * 2) = r;
}

extern "C" void kernel_launch(void* const* d_in, const int* in_sizes, int n_in,
                              void* d_out, int out_size) {
    const float* x   = (const float*)d_in[0];
    const int*   ei  = (const int*)d_in[1];     // int32, [2, E] row-major
    const float* W   = (const float*)d_in[2];
    const float* b   = (const float*)d_in[3];
    float*       out = (float*)d_out;

    int N = in_sizes[0] / C;     // 50000
    int E = in_sizes[1] / 2;     // 800000
    const int* src = ei;
    const int* tgt = ei + E;

    k_h<<<(N + 63) / 64, 64>>>(x, W, N);                 // also zeroes g_cnt/g_total
    k_deg<<<(E + 255) / 256, 256>>>(tgt, E);
    k_off<<<(N + 255) / 256, 256>>>(N);
    k_fill<<<(E + 255) / 256, 256>>>(src, tgt, E);

    long long T = (long long)N * 32;
    k_aggrelu<<<(int)((T + 255) / 256), 256>>>(b, out, N);
}

// round 11
// speedup vs baseline: 1.9211x; 1.1574x over previous
#include <cuda_runtime.h>

#define C 64
#define MAXN 50000
#define MAXE 800000

// Scratch (allocation-free, graph-safe). g_cnt/g_total are zero at module load
// and re-zeroed by k_aggrelu's epilogue every invocation (deterministic replay).
__device__ int   g_cnt[MAXN];                    // per-target degree
__device__ int   g_off[MAXN];                    // CSR segment starts (unordered)
__device__ float g_dis[MAXN];                    // deg_inv_sqrt
__device__ int   g_rank[MAXE];                   // edge's rank within its target
__device__ int   g_srcid[MAXE];                  // CSR: source id per slot
__device__ int   g_total;                        // global segment cursor
__device__ __align__(16) float g_h[MAXN * C];    // h' = dis[n] * (x @ W^T)[n]

// Degree histogram; atomicAdd's return value is this edge's rank within its target.
__global__ void k_deg(const int* __restrict__ tgt, int E) {
    int i = blockIdx.x * blockDim.x + threadIdx.x;
    if (i < E) g_rank[i] = atomicAdd(&g_cnt[tgt[i]], 1);
}

// Fused: CSR offsets (warp-scan + cursor atomic) + deg_inv_sqrt + h' = dis*(x@W^T).
// Block = 64 threads = 64 nodes; each warp scans its 32 nodes' counts.
__global__ void __launch_bounds__(64) k_h(const float* __restrict__ x,
                                          const float* __restrict__ W, int N) {
    __shared__ float Ws[C * C];        // Ws[k*64 + j] = W[j*64 + k]
    __shared__ float As[64][C + 1];
    __shared__ float Ds[64];           // dis for this block's 64 nodes
    int tid = threadIdx.x;
    int lane = tid & 31;
    int node = blockIdx.x * 64 + tid;

    // Offsets + dis for own node (scan-free global cursor; segment order unimportant).
    {
        int c = (node < N) ? g_cnt[node] : 0;
        int v = c;
        #pragma unroll
        for (int d = 1; d < 32; d <<= 1) {
            int u = __shfl_up_sync(0xffffffffu, v, d);
            if (lane >= d) v += u;
        }
        int wtot = __shfl_sync(0xffffffffu, v, 31);
        int wbase = 0;
        if (lane == 31) wbase = atomicAdd(&g_total, wtot);
        wbase = __shfl_sync(0xffffffffu, wbase, 31);
        float dis = rsqrtf(fmaxf((float)c, 1.0f));
        if (node < N) {
            g_off[node] = wbase + v - c;
            g_dis[node] = dis;
        }
        Ds[tid] = dis;
    }

    for (int idx = tid; idx < C * C; idx += 64) {
        int j = idx >> 6, k = idx & 63;
        Ws[k * C + j] = W[idx];
    }
    int base = blockIdx.x * 64;
    for (int idx = tid; idx < 64 * 16; idx += 64) {
        int i = idx >> 4, j4 = idx & 15;
        int r = base + i;
        float4 v = (r < N) ? ((const float4*)(x + (size_t)r * C))[j4]
                           : make_float4(0.f, 0.f, 0.f, 0.f);
        As[i][j4 * 4 + 0] = v.x;
        As[i][j4 * 4 + 1] = v.y;
        As[i][j4 * 4 + 2] = v.z;
        As[i][j4 * 4 + 3] = v.w;
    }
    __syncthreads();

    float acc[C];
    #pragma unroll
    for (int j = 0; j < C; j++) acc[j] = 0.0f;

    for (int k = 0; k < C; k++) {
        float ak = As[tid][k];
        const float4* wr = (const float4*)(Ws + k * C);
        #pragma unroll
        for (int j4 = 0; j4 < 16; j4++) {
            float4 w = wr[j4];
            acc[4 * j4 + 0] += ak * w.x;
            acc[4 * j4 + 1] += ak * w.y;
            acc[4 * j4 + 2] += ak * w.z;
            acc[4 * j4 + 3] += ak * w.w;
        }
    }

    if (node < N) {
        float dis = Ds[tid];
        float4* o = (float4*)(g_h + (size_t)node * C);
        #pragma unroll
        for (int j4 = 0; j4 < 16; j4++)
            o[j4] = make_float4(dis * acc[4 * j4],     dis * acc[4 * j4 + 1],
                                dis * acc[4 * j4 + 2], dis * acc[4 * j4 + 3]);
    }
}

// CSR fill, no atomics: slot = off[tgt] + rank; payload is just the 4B src id
// (dis[src] is pre-folded into h', so no scattered dis gather here).
__global__ void k_fill(const int* __restrict__ src, const int* __restrict__ tgt, int E) {
    int i = blockIdx.x * blockDim.x + threadIdx.x;
    if (i >= E) return;
    g_srcid[g_off[tgt[i]] + g_rank[i]] = src[i];
}

// Aggregate h' over CSR + dis[tgt] + bias + relu, writing d_out directly.
// One warp per node; uniform 4B id loads, independent float2 row gathers, unroll-4.
// Epilogue re-zeroes g_cnt/g_total for the next (deterministic) invocation.
__global__ void k_aggrelu(const float* __restrict__ bias, float* __restrict__ out, int N) {
    int w = (blockIdx.x * blockDim.x + threadIdx.x) >> 5;
    int lane = threadIdx.x & 31;
    if (w >= N) return;
    int off = g_off[w];
    int cnt = g_cnt[w];
    const float* hp = g_h + lane * 2;
    float a0 = 0.0f, a1 = 0.0f;
    int i = 0;
    for (; i + 4 <= cnt; i += 4) {
        int s0 = g_srcid[off + i];
        int s1 = g_srcid[off + i + 1];
        int s2 = g_srcid[off + i + 2];
        int s3 = g_srcid[off + i + 3];
        float2 v0 = *(const float2*)(hp + (size_t)s0 * C);
        float2 v1 = *(const float2*)(hp + (size_t)s1 * C);
        float2 v2 = *(const float2*)(hp + (size_t)s2 * C);
        float2 v3 = *(const float2*)(hp + (size_t)s3 * C);
        a0 += v0.x + v1.x + v2.x + v3.x;
        a1 += v0.y + v1.y + v2.y + v3.y;
    }
    for (; i < cnt; i++) {
        int s = g_srcid[off + i];
        float2 v = *(const float2*)(hp + (size_t)s * C);
        a0 += v.x;
        a1 += v.y;
    }

    float dn = g_dis[w];
    float2 bb = *(const float2*)(bias + lane * 2);
    float2 r;
    r.x = fmaxf(a0 * dn + bb.x, 0.0f);
    r.y = fmaxf(a1 * dn + bb.y, 0.0f);
    *(float2*)(out + (size_t)w * C + lane * 2) = r;

    // Restore zeros for next invocation (own node only; g_cnt[w] already consumed).
    if (lane == 0) {
        g_cnt[w] = 0;
        if (w == 0) g_total = 0;
    }
}

extern "C" void kernel_launch(void* const* d_in, const int* in_sizes, int n_in,
                              void* d_out, int out_size) {
    const float* x   = (const float*)d_in[0];
    const int*   ei  = (const int*)d_in[1];     // int32, [2, E] row-major
    const float* W   = (const float*)d_in[2];
    const float* b   = (const float*)d_in[3];
    float*       out = (float*)d_out;

    int N = in_sizes[0] / C;     // 50000
    int E = in_sizes[1] / 2;     // 800000
    const int* src = ei;
    const int* tgt = ei + E;

    k_deg<<<(E + 255) / 256, 256>>>(tgt, E);
    k_h<<<(N + 63) / 64, 64>>>(x, W, N);          // offsets + dis + scaled GEMM
    k_fill<<<(E + 255) / 256, 256>>>(src, tgt, E);

    long long T = (long long)N * 32;
    k_aggrelu<<<(int)((T + 255) / 256), 256>>>(b, out, N);
}